// round 4
// baseline (speedup 1.0000x reference)
#include <cuda_runtime.h>
#include <math_constants.h>

#define IMG_H 64
#define IMG_W 2048
#define KNN_CUTOFF 1.0f
#define P_CAP 131072

// inv_g[k] = 1 - gauss(k)/sum(gauss), sigma=1, 5x5, row-major (ky,kx)
__device__ __constant__ float INV_G_C[25] = {
    0.99703098f, 0.98669378f, 0.97806177f, 0.98669378f, 0.99703098f,
    0.98669378f, 0.94036569f, 0.90167956f, 0.94036569f, 0.98669378f,
    0.97806177f, 0.90167956f, 0.83789717f, 0.90167956f, 0.97806177f,
    0.98669378f, 0.94036569f, 0.90167956f, 0.94036569f, 0.98669378f,
    0.99703098f, 0.98669378f, 0.97806177f, 0.98669378f, 0.99703098f
};

// compile-time-foldable copy (immediates in FMUL, no LDC in hot path)
__device__ __forceinline__ constexpr float inv_g_k(int k) {
    constexpr float g[25] = {
        0.99703098f, 0.98669378f, 0.97806177f, 0.98669378f, 0.99703098f,
        0.98669378f, 0.94036569f, 0.90167956f, 0.94036569f, 0.98669378f,
        0.97806177f, 0.90167956f, 0.83789717f, 0.90167956f, 0.97806177f,
        0.98669378f, 0.94036569f, 0.90167956f, 0.94036569f, 0.98669378f,
        0.99703098f, 0.98669378f, 0.97806177f, 0.98669378f, 0.99703098f
    };
    return g[k];
}

// per point: 25-bit contribution mask (bit k set => pixel in window contributes)
__device__ unsigned g_mask[P_CAP];

// ---------------------------------------------------------------------------
// Kernel A: cutoff-mask selection. 1 thread/point.
// Fast path: <=5 below cutoff  => mask is exactly the cutoff set.
// Rare path (>5 below cutoff, ~5e-4): exact top-5 with index tiebreak.
// ---------------------------------------------------------------------------
__global__ __launch_bounds__(256)
void knn_select(const float* __restrict__ proj_range,
                const float* __restrict__ unproj,
                const int*   __restrict__ px,
                const int*   __restrict__ py,
                int P)
{
    int p = blockIdx.x * blockDim.x + threadIdx.x;
    if (p >= P) return;

    const int x0 = px[p];
    const int y0 = py[p];
    const float ur = unproj[p];

    unsigned mask = 0;   // d <= cutoff (with r<0 -> inf excluded)
    unsigned ib   = 0;   // in-bounds bits

    if (x0 >= 2 && x0 <= IMG_W - 3) {
        // interior: whole window in-row; 2 aligned float4 loads per row
        const int xb   = x0 - 2;
        const int base = xb & ~3;          // aligned, in [0, W-8] since W%4==0
        const bool b1  = (xb & 2) != 0;
        const bool b0  = (xb & 1) != 0;
#pragma unroll
        for (int row = 0; row < 5; ++row) {
            const int yy  = y0 + row - 2;
            const bool rv = ((unsigned)yy < (unsigned)IMG_H);
            const int yyc = rv ? yy : 0;
            const float4* rp = (const float4*)(proj_range + yyc * IMG_W + base);
            const float4 lo = __ldg(rp);
            const float4 hi = __ldg(rp + 1);
            // select window f[xb&3 .. xb&3+4] out of 8 via 2-level tree (11 SELs)
            const float h0 = b1 ? lo.z : lo.x;
            const float h1 = b1 ? lo.w : lo.y;
            const float h2 = b1 ? hi.x : lo.z;
            const float h3 = b1 ? hi.y : lo.w;
            const float h4 = b1 ? hi.z : hi.x;
            const float h5 = b1 ? hi.w : hi.y;
            float wv[5];
            wv[0] = b0 ? h1 : h0;
            wv[1] = b0 ? h2 : h1;
            wv[2] = b0 ? h3 : h2;
            wv[3] = b0 ? h4 : h3;
            wv[4] = b0 ? h5 : h4;
#pragma unroll
            for (int i = 0; i < 5; ++i) {
                const int k = row * 5 + i;
                const float r = rv ? wv[i] : 0.0f;
                const float d = fabsf(r - ur) * inv_g_k(k);
                if ((d <= KNN_CUTOFF) && (r >= 0.0f)) mask |= (1u << k);
                if (rv)                                ib   |= (1u << k);
            }
        }
    } else {
        // edge columns (~0.25% of points): scalar loads
#pragma unroll
        for (int k = 0; k < 25; ++k) {
            const int yy = y0 + (k / 5) - 2;
            const int xx = x0 + (k % 5) - 2;
            const bool valid = ((unsigned)yy < (unsigned)IMG_H) &&
                               ((unsigned)xx < (unsigned)IMG_W);
            const float r = valid ? __ldg(proj_range + yy * IMG_W + xx) : 0.0f;
            const float d = fabsf(r - ur) * inv_g_k(k);
            if ((d <= KNN_CUTOFF) && (r >= 0.0f)) mask |= (1u << k);
            if (valid)                             ib   |= (1u << k);
        }
    }

    mask |= (1u << 12);   // center: d forced to 0, always passes (always in-bounds)
    ib   |= (1u << 12);

    if (__popc(mask) > 5) {
        // exact top-5 (ascending value, lowest index on ties); all 5 winners
        // necessarily have d <= cutoff since >5 elements are below cutoff.
        unsigned nm = 0;
        for (int s = 0; s < 5; ++s) {
            unsigned long long best = ~0ull;
            int bi = 0;
            for (int k = 0; k < 25; ++k) {
                if (nm & (1u << k)) continue;
                float d;
                if (k == 12) {
                    d = 0.0f;
                } else {
                    const int yy = y0 + (k / 5) - 2;
                    const int xx = x0 + (k % 5) - 2;
                    const bool valid = ((unsigned)yy < (unsigned)IMG_H) &&
                                       ((unsigned)xx < (unsigned)IMG_W);
                    float r = valid ? __ldg(proj_range + yy * IMG_W + xx) : 0.0f;
                    if (r < 0.0f) r = CUDART_INF_F;
                    d = fabsf(r - ur) * INV_G_C[k];
                }
                const unsigned long long c =
                    ((unsigned long long)__float_as_uint(d) << 32) | (unsigned)k;
                if (c < best) { best = c; bi = k; }
            }
            nm |= (1u << bi);
        }
        mask = nm;
    }

    g_mask[p] = mask & ib;   // out-of-bounds winners contribute zero: drop them
}

// ---------------------------------------------------------------------------
// Kernel B: accumulation. 5 threads/point (one float4 chunk each).
// ---------------------------------------------------------------------------
__global__ __launch_bounds__(256)
void knn_gather(const float4* __restrict__ probs4,   // [H*W][5] float4 (=20 ch)
                const int*    __restrict__ px,
                const int*    __restrict__ py,
                float4*       __restrict__ out4,     // [P][5] float4
                int P)
{
    int t = blockIdx.x * blockDim.x + threadIdx.x;
    if (t >= P * 5) return;

    const int p = t / 5;
    const int c = t - p * 5;

    unsigned m = g_mask[p];
    const int x0 = px[p];
    const int y0 = py[p];

    float4 acc = make_float4(0.f, 0.f, 0.f, 0.f);
    while (m) {
        const int k  = __ffs(m) - 1;
        m &= m - 1;
        const int ky = (k * 205) >> 10;       // k / 5
        const int kx = k - ky * 5;
        const int yy = y0 + ky - 2;
        const int xx = x0 + kx - 2;
        const float4 v = __ldg(probs4 + (size_t)(yy * IMG_W + xx) * 5 + c);
        acc.x += v.x; acc.y += v.y; acc.z += v.z; acc.w += v.w;
    }

    out4[t] = acc;   // fully coalesced
}

extern "C" void kernel_launch(void* const* d_in, const int* in_sizes, int n_in,
                              void* d_out, int out_size)
{
    const float*  proj_range = (const float*)  d_in[0];
    const float*  unproj     = (const float*)  d_in[1];
    const float4* probs4     = (const float4*) d_in[2];
    const int*    px         = (const int*)    d_in[3];
    const int*    py         = (const int*)    d_in[4];
    float4*       out4       = (float4*)       d_out;

    int P = in_sizes[1];                 // unproj_range element count
    if (P > P_CAP) P = P_CAP;            // scratch capacity guard (fixed-shape problem)

    {
        const int threads = 256;
        const int blocks = (P + threads - 1) / threads;
        knn_select<<<blocks, threads>>>(proj_range, unproj, px, py, P);
    }
    {
        const int threads = 256;
        const int total = P * 5;
        const int blocks = (total + threads - 1) / threads;
        knn_gather<<<blocks, threads>>>(probs4, px, py, out4, P);
    }
}

// round 5
// speedup vs baseline: 1.0031x; 1.0031x over previous
#include <cuda_runtime.h>
#include <math_constants.h>

#define IMG_H 64
#define IMG_W 2048
#define KNN_CUTOFF 1.0f
#define P_CAP 131072

// inv_g[k] = 1 - gauss(k)/sum(gauss), sigma=1, 5x5, row-major (ky,kx)
__device__ __constant__ float INV_G_C[25] = {
    0.99703098f, 0.98669378f, 0.97806177f, 0.98669378f, 0.99703098f,
    0.98669378f, 0.94036569f, 0.90167956f, 0.94036569f, 0.98669378f,
    0.97806177f, 0.90167956f, 0.83789717f, 0.90167956f, 0.97806177f,
    0.98669378f, 0.94036569f, 0.90167956f, 0.94036569f, 0.98669378f,
    0.99703098f, 0.98669378f, 0.97806177f, 0.98669378f, 0.99703098f
};

// compile-time-foldable copy (immediates in FMUL, no LDC in hot path)
__device__ __forceinline__ constexpr float inv_g_k(int k) {
    constexpr float g[25] = {
        0.99703098f, 0.98669378f, 0.97806177f, 0.98669378f, 0.99703098f,
        0.98669378f, 0.94036569f, 0.90167956f, 0.94036569f, 0.98669378f,
        0.97806177f, 0.90167956f, 0.83789717f, 0.90167956f, 0.97806177f,
        0.98669378f, 0.94036569f, 0.90167956f, 0.94036569f, 0.98669378f,
        0.99703098f, 0.98669378f, 0.97806177f, 0.98669378f, 0.99703098f
    };
    return g[k];
}

// per point: 25-bit contribution mask (bit k set => pixel in window contributes)
__device__ unsigned g_mask[P_CAP];

// ---------------------------------------------------------------------------
// Kernel A: cutoff-mask selection. 1 thread/point.
// Fast path: <=5 below cutoff  => mask is exactly the cutoff set.
// Rare path (>5 below cutoff, ~5e-4): exact top-5 with index tiebreak.
// ---------------------------------------------------------------------------
__global__ __launch_bounds__(256)
void knn_select(const float* __restrict__ proj_range,
                const float* __restrict__ unproj,
                const int*   __restrict__ px,
                const int*   __restrict__ py,
                int P)
{
    int p = blockIdx.x * blockDim.x + threadIdx.x;
    if (p >= P) return;

    const int x0 = px[p];
    const int y0 = py[p];
    const float ur = unproj[p];

    unsigned mask = 0;   // d <= cutoff (with r<0 -> inf excluded)
    unsigned ib   = 0;   // in-bounds bits

    if (x0 >= 2 && x0 <= IMG_W - 3) {
        // interior: whole window in-row; 2 aligned float4 loads per row
        const int xb   = x0 - 2;
        const int base = xb & ~3;          // aligned, in [0, W-8] since W%4==0
        const bool b1  = (xb & 2) != 0;
        const bool b0  = (xb & 1) != 0;
#pragma unroll
        for (int row = 0; row < 5; ++row) {
            const int yy  = y0 + row - 2;
            const bool rv = ((unsigned)yy < (unsigned)IMG_H);
            const int yyc = rv ? yy : 0;
            const float4* rp = (const float4*)(proj_range + yyc * IMG_W + base);
            const float4 lo = __ldg(rp);
            const float4 hi = __ldg(rp + 1);
            // select window f[xb&3 .. xb&3+4] out of 8 via 2-level tree (11 SELs)
            const float h0 = b1 ? lo.z : lo.x;
            const float h1 = b1 ? lo.w : lo.y;
            const float h2 = b1 ? hi.x : lo.z;
            const float h3 = b1 ? hi.y : lo.w;
            const float h4 = b1 ? hi.z : hi.x;
            const float h5 = b1 ? hi.w : hi.y;
            float wv[5];
            wv[0] = b0 ? h1 : h0;
            wv[1] = b0 ? h2 : h1;
            wv[2] = b0 ? h3 : h2;
            wv[3] = b0 ? h4 : h3;
            wv[4] = b0 ? h5 : h4;
#pragma unroll
            for (int i = 0; i < 5; ++i) {
                const int k = row * 5 + i;
                const float r = rv ? wv[i] : 0.0f;
                const float d = fabsf(r - ur) * inv_g_k(k);
                if ((d <= KNN_CUTOFF) && (r >= 0.0f)) mask |= (1u << k);
                if (rv)                                ib   |= (1u << k);
            }
        }
    } else {
        // edge columns (~0.25% of points): scalar loads
#pragma unroll
        for (int k = 0; k < 25; ++k) {
            const int yy = y0 + (k / 5) - 2;
            const int xx = x0 + (k % 5) - 2;
            const bool valid = ((unsigned)yy < (unsigned)IMG_H) &&
                               ((unsigned)xx < (unsigned)IMG_W);
            const float r = valid ? __ldg(proj_range + yy * IMG_W + xx) : 0.0f;
            const float d = fabsf(r - ur) * inv_g_k(k);
            if ((d <= KNN_CUTOFF) && (r >= 0.0f)) mask |= (1u << k);
            if (valid)                             ib   |= (1u << k);
        }
    }

    mask |= (1u << 12);   // center: d forced to 0, always passes (always in-bounds)
    ib   |= (1u << 12);

    if (__popc(mask) > 5) {
        // exact top-5 (ascending value, lowest index on ties); all 5 winners
        // necessarily have d <= cutoff since >5 elements are below cutoff.
        unsigned nm = 0;
        for (int s = 0; s < 5; ++s) {
            unsigned long long best = ~0ull;
            int bi = 0;
            for (int k = 0; k < 25; ++k) {
                if (nm & (1u << k)) continue;
                float d;
                if (k == 12) {
                    d = 0.0f;
                } else {
                    const int yy = y0 + (k / 5) - 2;
                    const int xx = x0 + (k % 5) - 2;
                    const bool valid = ((unsigned)yy < (unsigned)IMG_H) &&
                                       ((unsigned)xx < (unsigned)IMG_W);
                    float r = valid ? __ldg(proj_range + yy * IMG_W + xx) : 0.0f;
                    if (r < 0.0f) r = CUDART_INF_F;
                    d = fabsf(r - ur) * INV_G_C[k];
                }
                const unsigned long long c =
                    ((unsigned long long)__float_as_uint(d) << 32) | (unsigned)k;
                if (c < best) { best = c; bi = k; }
            }
            nm |= (1u << bi);
        }
        mask = nm;
    }

    g_mask[p] = mask & ib;   // out-of-bounds winners contribute zero: drop them
}

// ---------------------------------------------------------------------------
// Kernel B: accumulation. 5 threads/point (one float4 chunk each).
// ---------------------------------------------------------------------------
__global__ __launch_bounds__(256)
void knn_gather(const float4* __restrict__ probs4,   // [H*W][5] float4 (=20 ch)
                const int*    __restrict__ px,
                const int*    __restrict__ py,
                float4*       __restrict__ out4,     // [P][5] float4
                int P)
{
    int t = blockIdx.x * blockDim.x + threadIdx.x;
    if (t >= P * 5) return;

    const int p = t / 5;
    const int c = t - p * 5;

    unsigned m = g_mask[p];
    const int x0 = px[p];
    const int y0 = py[p];

    float4 acc = make_float4(0.f, 0.f, 0.f, 0.f);
    while (m) {
        const int k  = __ffs(m) - 1;
        m &= m - 1;
        const int ky = (k * 205) >> 10;       // k / 5
        const int kx = k - ky * 5;
        const int yy = y0 + ky - 2;
        const int xx = x0 + kx - 2;
        const float4 v = __ldg(probs4 + (size_t)(yy * IMG_W + xx) * 5 + c);
        acc.x += v.x; acc.y += v.y; acc.z += v.z; acc.w += v.w;
    }

    out4[t] = acc;   // fully coalesced
}

extern "C" void kernel_launch(void* const* d_in, const int* in_sizes, int n_in,
                              void* d_out, int out_size)
{
    const float*  proj_range = (const float*)  d_in[0];
    const float*  unproj     = (const float*)  d_in[1];
    const float4* probs4     = (const float4*) d_in[2];
    const int*    px         = (const int*)    d_in[3];
    const int*    py         = (const int*)    d_in[4];
    float4*       out4       = (float4*)       d_out;

    int P = in_sizes[1];                 // unproj_range element count
    if (P > P_CAP) P = P_CAP;            // scratch capacity guard (fixed-shape problem)

    {
        const int threads = 256;
        const int blocks = (P + threads - 1) / threads;
        knn_select<<<blocks, threads>>>(proj_range, unproj, px, py, P);
    }
    {
        const int threads = 256;
        const int total = P * 5;
        const int blocks = (total + threads - 1) / threads;
        knn_gather<<<blocks, threads>>>(probs4, px, py, out4, P);
    }
}